// round 2
// baseline (speedup 1.0000x reference)
#include <cuda_runtime.h>

#define N_PATHS 1000000
#define N_LINKS 50000
#define K_HOPS  8

// Scratch: __device__ globals (no runtime allocation allowed).
__device__ float g_T[N_LINKS];
__device__ float g_bp[N_LINKS];
__device__ float g_rho[N_LINKS];
__device__ float g_Xl[N_LINKS];

__global__ void init_kernel() {
    int l = blockIdx.x * blockDim.x + threadIdx.x;
    if (l < N_LINKS) {
        g_T[l]  = 0.0f;
        g_bp[l] = 0.5f;
    }
}

// Streaming int4 load (evict-first): keeps the 32MB edge stream out of L1 so
// the 200KB g_bp / g_Xl arrays stay L1-resident for the random gathers.
__device__ __forceinline__ int4 ldcs_int4(const int4* p) {
    return __ldcs(p);
}

// One pass of update_traffic: each thread walks 4 paths through their 8 hops.
// T[e] += t (RED), then t *= (1 - bp[e]).
__global__ void __launch_bounds__(256) traffic_kernel(const float* __restrict__ P,
                                                      const int*   __restrict__ edges) {
    int p0 = (blockIdx.x * blockDim.x + threadIdx.x) * 4;
    if (p0 >= N_PATHS) return;

    // A = P[:,1]; P is (N_PATHS, 3) row-major. Stream these (one-shot use).
    float t0 = __ldcs(&P[3 * p0 + 1]);
    float t1 = __ldcs(&P[3 * p0 + 4]);
    float t2 = __ldcs(&P[3 * p0 + 7]);
    float t3 = __ldcs(&P[3 * p0 + 10]);

#pragma unroll
    for (int k = 0; k < K_HOPS; k++) {
        int4 e4 = ldcs_int4(reinterpret_cast<const int4*>(edges + (size_t)k * N_PATHS + p0));
        int e0 = e4.x - N_PATHS;
        int e1 = e4.y - N_PATHS;
        int e2 = e4.z - N_PATHS;
        int e3 = e4.w - N_PATHS;

        atomicAdd(&g_T[e0], t0);
        atomicAdd(&g_T[e1], t1);
        atomicAdd(&g_T[e2], t2);
        atomicAdd(&g_T[e3], t3);

        // Default-cached: g_bp (200KB) stays resident in the 228KB L1.
        t0 *= 1.0f - __ldg(&g_bp[e0]);
        t1 *= 1.0f - __ldg(&g_bp[e1]);
        t2 *= 1.0f - __ldg(&g_bp[e2]);
        t3 *= 1.0f - __ldg(&g_bp[e3]);
    }
}

// rho = T/cap ; bp = (1-rho)*rho^32 / (1 - rho^33 + 1e-8). Also re-zero T.
__global__ void link_update_kernel(const float* __restrict__ L) {
    int l = blockIdx.x * blockDim.x + threadIdx.x;
    if (l >= N_LINKS) return;

    float Tl = g_T[l];
    g_T[l] = 0.0f;

    float cap = __ldg(&L[l]) / 1000.0f;
    float rho = Tl / cap;

    float r2  = rho * rho;
    float r4  = r2 * r2;
    float r8  = r4 * r4;
    float r16 = r8 * r8;
    float r32 = r16 * r16;

    float denom = 1.0f - r32 * rho + 1e-8f;
    g_bp[l]  = (1.0f - rho) * r32 / denom;
    g_rho[l] = rho;
}

// Final per-link outputs: Lq, rho, pi0_final stacked, plus X_l for the path pass.
__global__ void final_link_kernel(const float* __restrict__ L,
                                  float* __restrict__ out) {
    int l = blockIdx.x * blockDim.x + threadIdx.x;
    if (l >= N_LINKS) return;

    float rho = g_rho[l];
    float r2  = rho * rho;
    float r4  = r2 * r2;
    float r8  = r4 * r4;
    float r16 = r8 * r8;
    float r32 = r16 * r16;
    float r33 = r32 * rho;

    float pi0 = (1.0f - rho) / (1.0f - r33);

    // s = sum_{m=0..32} coeff(m) * rho^m, coeff(0)=1, coeff(m)=m for m>=1
    float s  = 1.0f;
    float pw = 1.0f;
#pragma unroll
    for (int m = 1; m <= 32; m++) {
        pw *= rho;
        s  += (float)m * pw;
    }

    float Lq   = pi0 * s / 32.0f;
    float pi0f = pi0 * r32;
    float Xl   = Lq * 32000.0f / __ldg(&L[l]);

    g_Xl[l] = Xl;

    out[N_PATHS + 3 * l + 0] = Lq;
    out[N_PATHS + 3 * l + 1] = rho;
    out[N_PATHS + 3 * l + 2] = pi0f;
}

// res[p] = sum_k X_l[e[k,p]]   (pl_paths is identity -> plain gather-sum per path)
__global__ void __launch_bounds__(256) final_path_kernel(const int* __restrict__ edges,
                                                         float* __restrict__ out) {
    int p0 = (blockIdx.x * blockDim.x + threadIdx.x) * 4;
    if (p0 >= N_PATHS) return;

    float s0 = 0.0f, s1 = 0.0f, s2 = 0.0f, s3 = 0.0f;
#pragma unroll
    for (int k = 0; k < K_HOPS; k++) {
        int4 e4 = ldcs_int4(reinterpret_cast<const int4*>(edges + (size_t)k * N_PATHS + p0));
        s0 += __ldg(&g_Xl[e4.x - N_PATHS]);
        s1 += __ldg(&g_Xl[e4.y - N_PATHS]);
        s2 += __ldg(&g_Xl[e4.z - N_PATHS]);
        s3 += __ldg(&g_Xl[e4.w - N_PATHS]);
    }
    // Streaming stores: output is write-once, keep it out of L1.
    __stcs(&out[p0 + 0], s0);
    __stcs(&out[p0 + 1], s1);
    __stcs(&out[p0 + 2], s2);
    __stcs(&out[p0 + 3], s3);
}

extern "C" void kernel_launch(void* const* d_in, const int* in_sizes, int n_in,
                              void* d_out, int out_size) {
    const float* P     = (const float*)d_in[0];   // (N_PATHS, 3)
    const float* L     = (const float*)d_in[1];   // (N_LINKS, 1)
    // d_in[2] = pl_paths: identity, unused
    const int*   edges = (const int*)d_in[3];     // (K_HOPS, N_PATHS)
    float* out = (float*)d_out;

    const int LB = (N_LINKS + 255) / 256;
    const int PB = (N_PATHS / 4 + 255) / 256;

    init_kernel<<<LB, 256>>>();
    for (int it = 0; it < 3; it++) {
        traffic_kernel<<<PB, 256>>>(P, edges);
        link_update_kernel<<<LB, 256>>>(L);
    }
    final_link_kernel<<<LB, 256>>>(L, out);
    final_path_kernel<<<PB, 256>>>(edges, out);
}

// round 3
// speedup vs baseline: 1.5041x; 1.5041x over previous
#include <cuda_runtime.h>

#define N_PATHS 1000000
#define N_LINKS 50000
#define K_HOPS  8
#define N_REP   4

// Scratch: __device__ globals (no runtime allocation allowed).
__device__ float g_T[N_REP][N_LINKS];   // replicated accumulators (contention relief)
__device__ float g_bp[N_LINKS];
__device__ float g_rho[N_LINKS];
__device__ float g_Xl[N_LINKS];

__global__ void init_kernel() {
    int l = blockIdx.x * blockDim.x + threadIdx.x;
    if (l < N_LINKS) {
#pragma unroll
        for (int r = 0; r < N_REP; r++) g_T[r][l] = 0.0f;
        g_bp[l] = 0.5f;
    }
}

// Pass 1 specialization: bp == 0.5 everywhere, so t_k = A[p] * 0.5^k with NO
// gathers and no dependency chain. Pure scatter-add.
__global__ void __launch_bounds__(256) traffic_pass1_kernel(const float* __restrict__ P,
                                                            const int*   __restrict__ edges) {
    int p0 = (blockIdx.x * blockDim.x + threadIdx.x) * 4;
    if (p0 >= N_PATHS) return;
    int rep = threadIdx.x & (N_REP - 1);
    float* __restrict__ T = g_T[rep];

    float t0 = __ldg(&P[3 * p0 + 1]);
    float t1 = __ldg(&P[3 * p0 + 4]);
    float t2 = __ldg(&P[3 * p0 + 7]);
    float t3 = __ldg(&P[3 * p0 + 10]);

#pragma unroll
    for (int k = 0; k < K_HOPS; k++) {
        int4 e4 = *reinterpret_cast<const int4*>(edges + (size_t)k * N_PATHS + p0);
        atomicAdd(&T[e4.x - N_PATHS], t0);
        atomicAdd(&T[e4.y - N_PATHS], t1);
        atomicAdd(&T[e4.z - N_PATHS], t2);
        atomicAdd(&T[e4.w - N_PATHS], t3);
        t0 *= 0.5f; t1 *= 0.5f; t2 *= 0.5f; t3 *= 0.5f;
    }
}

// General pass: T[e] += t (RED), then t *= (1 - bp[e]). bp stays L1-resident.
__global__ void __launch_bounds__(256) traffic_kernel(const float* __restrict__ P,
                                                      const int*   __restrict__ edges) {
    int p0 = (blockIdx.x * blockDim.x + threadIdx.x) * 4;
    if (p0 >= N_PATHS) return;
    int rep = threadIdx.x & (N_REP - 1);
    float* __restrict__ T = g_T[rep];

    float t0 = __ldg(&P[3 * p0 + 1]);
    float t1 = __ldg(&P[3 * p0 + 4]);
    float t2 = __ldg(&P[3 * p0 + 7]);
    float t3 = __ldg(&P[3 * p0 + 10]);

#pragma unroll
    for (int k = 0; k < K_HOPS; k++) {
        int4 e4 = *reinterpret_cast<const int4*>(edges + (size_t)k * N_PATHS + p0);
        int e0 = e4.x - N_PATHS;
        int e1 = e4.y - N_PATHS;
        int e2 = e4.z - N_PATHS;
        int e3 = e4.w - N_PATHS;

        atomicAdd(&T[e0], t0);
        atomicAdd(&T[e1], t1);
        atomicAdd(&T[e2], t2);
        atomicAdd(&T[e3], t3);

        t0 *= 1.0f - __ldg(&g_bp[e0]);
        t1 *= 1.0f - __ldg(&g_bp[e1]);
        t2 *= 1.0f - __ldg(&g_bp[e2]);
        t3 *= 1.0f - __ldg(&g_bp[e3]);
    }
}

// rho = T/cap ; bp = (1-rho)*rho^32 / (1 - rho^33 + 1e-8). Sum replicas, re-zero.
__global__ void link_update_kernel(const float* __restrict__ L) {
    int l = blockIdx.x * blockDim.x + threadIdx.x;
    if (l >= N_LINKS) return;

    float Tl = 0.0f;
#pragma unroll
    for (int r = 0; r < N_REP; r++) { Tl += g_T[r][l]; g_T[r][l] = 0.0f; }

    float cap = __ldg(&L[l]) / 1000.0f;
    float rho = Tl / cap;

    float r2  = rho * rho;
    float r4  = r2 * r2;
    float r8  = r4 * r4;
    float r16 = r8 * r8;
    float r32 = r16 * r16;

    float denom = 1.0f - r32 * rho + 1e-8f;
    g_bp[l]  = (1.0f - rho) * r32 / denom;
    g_rho[l] = rho;
}

// Final per-link outputs: Lq, rho, pi0_final stacked, plus X_l for the path pass.
__global__ void final_link_kernel(const float* __restrict__ L,
                                  float* __restrict__ out) {
    int l = blockIdx.x * blockDim.x + threadIdx.x;
    if (l >= N_LINKS) return;

    float rho = g_rho[l];
    float r2  = rho * rho;
    float r4  = r2 * r2;
    float r8  = r4 * r4;
    float r16 = r8 * r8;
    float r32 = r16 * r16;
    float r33 = r32 * rho;

    float pi0 = (1.0f - rho) / (1.0f - r33);

    float s  = 1.0f;
    float pw = 1.0f;
#pragma unroll
    for (int m = 1; m <= 32; m++) {
        pw *= rho;
        s  += (float)m * pw;
    }

    float Lq   = pi0 * s / 32.0f;
    float pi0f = pi0 * r32;
    float Xl   = Lq * 32000.0f / __ldg(&L[l]);

    g_Xl[l] = Xl;

    out[N_PATHS + 3 * l + 0] = Lq;
    out[N_PATHS + 3 * l + 1] = rho;
    out[N_PATHS + 3 * l + 2] = pi0f;
}

// res[p] = sum_k X_l[e[k,p]]   (pl_paths is identity -> plain gather-sum per path)
__global__ void __launch_bounds__(256) final_path_kernel(const int* __restrict__ edges,
                                                         float* __restrict__ out) {
    int p0 = (blockIdx.x * blockDim.x + threadIdx.x) * 4;
    if (p0 >= N_PATHS) return;

    float s0 = 0.0f, s1 = 0.0f, s2 = 0.0f, s3 = 0.0f;
#pragma unroll
    for (int k = 0; k < K_HOPS; k++) {
        int4 e4 = *reinterpret_cast<const int4*>(edges + (size_t)k * N_PATHS + p0);
        s0 += __ldg(&g_Xl[e4.x - N_PATHS]);
        s1 += __ldg(&g_Xl[e4.y - N_PATHS]);
        s2 += __ldg(&g_Xl[e4.z - N_PATHS]);
        s3 += __ldg(&g_Xl[e4.w - N_PATHS]);
    }
    out[p0 + 0] = s0;
    out[p0 + 1] = s1;
    out[p0 + 2] = s2;
    out[p0 + 3] = s3;
}

extern "C" void kernel_launch(void* const* d_in, const int* in_sizes, int n_in,
                              void* d_out, int out_size) {
    const float* P     = (const float*)d_in[0];   // (N_PATHS, 3)
    const float* L     = (const float*)d_in[1];   // (N_LINKS, 1)
    // d_in[2] = pl_paths: identity, unused
    const int*   edges = (const int*)d_in[3];     // (K_HOPS, N_PATHS)
    float* out = (float*)d_out;

    const int LB = (N_LINKS + 255) / 256;
    const int PB = (N_PATHS / 4 + 255) / 256;

    init_kernel<<<LB, 256>>>();

    traffic_pass1_kernel<<<PB, 256>>>(P, edges);   // bp == 0.5 exactly
    link_update_kernel<<<LB, 256>>>(L);

    traffic_kernel<<<PB, 256>>>(P, edges);
    link_update_kernel<<<LB, 256>>>(L);

    traffic_kernel<<<PB, 256>>>(P, edges);
    link_update_kernel<<<LB, 256>>>(L);

    final_link_kernel<<<LB, 256>>>(L, out);
    final_path_kernel<<<PB, 256>>>(edges, out);
}

// round 4
// speedup vs baseline: 1.5845x; 1.0534x over previous
#include <cuda_runtime.h>

#define N_PATHS 1000000
#define N_LINKS 50000
#define K_HOPS  8
#define N_REP   8

// Scratch: __device__ globals. Zero-initialized at module load; every
// link_update re-zeroes g_T, so "g_T == 0 on entry" is a maintained invariant
// across graph replays (no init kernel needed). g_bp is written by the first
// link_update before its first read (pass-1 traffic is specialized to bp=0.5).
__device__ float g_T[N_REP][N_LINKS];
__device__ float g_bp[N_LINKS];
__device__ float g_rho[N_LINKS];
__device__ float g_Xl[N_LINKS];

// Pass 1: bp == 0.5 everywhere -> t_k = A[p] * 0.5^k, no gathers, no dep chain.
__global__ void __launch_bounds__(128) traffic_pass1_kernel(const float* __restrict__ P,
                                                            const int*   __restrict__ edges) {
    int p0 = (blockIdx.x * blockDim.x + threadIdx.x) * 4;
    if (p0 >= N_PATHS) return;
    float* __restrict__ T = g_T[threadIdx.x & (N_REP - 1)];

    float t0 = __ldg(&P[3 * p0 + 1]);
    float t1 = __ldg(&P[3 * p0 + 4]);
    float t2 = __ldg(&P[3 * p0 + 7]);
    float t3 = __ldg(&P[3 * p0 + 10]);

#pragma unroll
    for (int k = 0; k < K_HOPS; k++) {
        int4 e4 = *reinterpret_cast<const int4*>(edges + (size_t)k * N_PATHS + p0);
        atomicAdd(&T[e4.x - N_PATHS], t0);
        atomicAdd(&T[e4.y - N_PATHS], t1);
        atomicAdd(&T[e4.z - N_PATHS], t2);
        atomicAdd(&T[e4.w - N_PATHS], t3);
        t0 *= 0.5f; t1 *= 0.5f; t2 *= 0.5f; t3 *= 0.5f;
    }
}

// General pass: T[e] += t (RED into one of 8 replicas), then t *= (1 - bp[e]).
__global__ void __launch_bounds__(128) traffic_kernel(const float* __restrict__ P,
                                                      const int*   __restrict__ edges) {
    int p0 = (blockIdx.x * blockDim.x + threadIdx.x) * 4;
    if (p0 >= N_PATHS) return;
    float* __restrict__ T = g_T[threadIdx.x & (N_REP - 1)];

    float t0 = __ldg(&P[3 * p0 + 1]);
    float t1 = __ldg(&P[3 * p0 + 4]);
    float t2 = __ldg(&P[3 * p0 + 7]);
    float t3 = __ldg(&P[3 * p0 + 10]);

#pragma unroll
    for (int k = 0; k < K_HOPS; k++) {
        int4 e4 = *reinterpret_cast<const int4*>(edges + (size_t)k * N_PATHS + p0);
        int e0 = e4.x - N_PATHS;
        int e1 = e4.y - N_PATHS;
        int e2 = e4.z - N_PATHS;
        int e3 = e4.w - N_PATHS;

        atomicAdd(&T[e0], t0);
        atomicAdd(&T[e1], t1);
        atomicAdd(&T[e2], t2);
        atomicAdd(&T[e3], t3);

        t0 *= 1.0f - __ldg(&g_bp[e0]);
        t1 *= 1.0f - __ldg(&g_bp[e1]);
        t2 *= 1.0f - __ldg(&g_bp[e2]);
        t3 *= 1.0f - __ldg(&g_bp[e3]);
    }
}

// Mid-iteration link update: rho = (sum_r T_r)/cap, bp = (1-rho)rho^32/(1-rho^33+1e-8).
// Re-zeroes g_T for the next pass.
__global__ void link_update_kernel(const float* __restrict__ L) {
    int l = blockIdx.x * blockDim.x + threadIdx.x;
    if (l >= N_LINKS) return;

    float Tl = 0.0f;
#pragma unroll
    for (int r = 0; r < N_REP; r++) { Tl += g_T[r][l]; g_T[r][l] = 0.0f; }

    float cap = __ldg(&L[l]) / 1000.0f;
    float rho = Tl / cap;

    float r2  = rho * rho;
    float r4  = r2 * r2;
    float r8  = r4 * r4;
    float r16 = r8 * r8;
    float r32 = r16 * r16;

    g_bp[l]  = (1.0f - rho) * r32 / (1.0f - r32 * rho + 1e-8f);
    g_rho[l] = rho;
}

// Final link update (iteration 3), fused with the per-link epilogue:
// computes rho, then Lq / pi0_final / X_l and writes the stacked output.
__global__ void link_update_final_kernel(const float* __restrict__ L,
                                         float* __restrict__ out) {
    int l = blockIdx.x * blockDim.x + threadIdx.x;
    if (l >= N_LINKS) return;

    float Tl = 0.0f;
#pragma unroll
    for (int r = 0; r < N_REP; r++) { Tl += g_T[r][l]; g_T[r][l] = 0.0f; }

    float Lraw = __ldg(&L[l]);
    float cap  = Lraw / 1000.0f;
    float rho  = Tl / cap;

    float r2  = rho * rho;
    float r4  = r2 * r2;
    float r8  = r4 * r4;
    float r16 = r8 * r8;
    float r32 = r16 * r16;
    float r33 = r32 * rho;

    float pi0 = (1.0f - rho) / (1.0f - r33);

    // s = 1 + sum_{m=1..32} m * rho^m
    float s  = 1.0f;
    float pw = 1.0f;
#pragma unroll
    for (int m = 1; m <= 32; m++) {
        pw *= rho;
        s  += (float)m * pw;
    }

    float Lq   = pi0 * s / 32.0f;
    float pi0f = pi0 * r32;
    float Xl   = Lq * 32000.0f / Lraw;

    g_Xl[l] = Xl;

    out[N_PATHS + 3 * l + 0] = Lq;
    out[N_PATHS + 3 * l + 1] = rho;
    out[N_PATHS + 3 * l + 2] = pi0f;
}

// res[p] = sum_k X_l[e[k,p]]  (pl_paths is identity -> plain gather-sum)
__global__ void __launch_bounds__(128) final_path_kernel(const int* __restrict__ edges,
                                                         float* __restrict__ out) {
    int p0 = (blockIdx.x * blockDim.x + threadIdx.x) * 4;
    if (p0 >= N_PATHS) return;

    float s0 = 0.0f, s1 = 0.0f, s2 = 0.0f, s3 = 0.0f;
#pragma unroll
    for (int k = 0; k < K_HOPS; k++) {
        int4 e4 = *reinterpret_cast<const int4*>(edges + (size_t)k * N_PATHS + p0);
        s0 += __ldg(&g_Xl[e4.x - N_PATHS]);
        s1 += __ldg(&g_Xl[e4.y - N_PATHS]);
        s2 += __ldg(&g_Xl[e4.z - N_PATHS]);
        s3 += __ldg(&g_Xl[e4.w - N_PATHS]);
    }
    out[p0 + 0] = s0;
    out[p0 + 1] = s1;
    out[p0 + 2] = s2;
    out[p0 + 3] = s3;
}

extern "C" void kernel_launch(void* const* d_in, const int* in_sizes, int n_in,
                              void* d_out, int out_size) {
    const float* P     = (const float*)d_in[0];   // (N_PATHS, 3)
    const float* L     = (const float*)d_in[1];   // (N_LINKS, 1)
    // d_in[2] = pl_paths: identity, unused
    const int*   edges = (const int*)d_in[3];     // (K_HOPS, N_PATHS)
    float* out = (float*)d_out;

    const int LB = (N_LINKS + 255) / 256;
    const int PB = (N_PATHS / 4 + 127) / 128;     // 1954 CTAs of 128 thr -> 1 wave

    traffic_pass1_kernel<<<PB, 128>>>(P, edges);  // bp == 0.5 exactly
    link_update_kernel<<<LB, 256>>>(L);

    traffic_kernel<<<PB, 128>>>(P, edges);
    link_update_kernel<<<LB, 256>>>(L);

    traffic_kernel<<<PB, 128>>>(P, edges);
    link_update_final_kernel<<<LB, 256>>>(L, out);

    final_path_kernel<<<PB, 128>>>(edges, out);
}